// round 2
// baseline (speedup 1.0000x reference)
#include <cuda_runtime.h>
#include <cuda_bf16.h>

// Problem constants: B=1, C=256, N=16*16*16=4096, heads=8, d=32
#define NTOK 4096
#define CCH  256
#define NHEAD 8
#define HDIM 32

// Scratch (device globals; no allocation allowed)
// q,k,v stored as [head][n][d] : h*131072 + n*32 + dd
__device__ float g_q[NHEAD * NTOK * HDIM];
__device__ float g_k[NHEAD * NTOK * HDIM];
__device__ float g_v[NHEAD * NTOK * HDIM];
// attn output stored as [c][n] (same layout as x) for the O projection
__device__ float g_attn[CCH * NTOK];

// ---------------------------------------------------------------------------
// QKV projection: y[o][n] = sum_c W[o][c] * x[c][n] + b[o]
// stored transposed into [head][n][d] layout.
// Tile: 64 out-channels x 64 tokens, BK=16, 256 threads, 4x4 microtile.
// blockIdx.z selects Q/K/V.
// ---------------------------------------------------------------------------
__global__ void __launch_bounds__(256) proj_qkv_kernel(
    const float* __restrict__ x,
    const float* __restrict__ Wq, const float* __restrict__ bq,
    const float* __restrict__ Wk, const float* __restrict__ bk,
    const float* __restrict__ Wv, const float* __restrict__ bv)
{
    const float* W; const float* b; float* outp;
    if (blockIdx.z == 0)      { W = Wq; b = bq; outp = g_q; }
    else if (blockIdx.z == 1) { W = Wk; b = bk; outp = g_k; }
    else                      { W = Wv; b = bv; outp = g_v; }

    __shared__ float Ws[16][64];   // [k][o]
    __shared__ float Xs[16][64];   // [k][n]

    const int tid = threadIdx.x;
    const int o0 = blockIdx.y * 64;
    const int n0 = blockIdx.x * 64;
    const int to = (tid >> 4) * 4;      // 0..60
    const int tn = (tid & 15) * 4;      // 0..60

    // load-index mapping
    const int wrow = tid >> 2;          // 0..63  (out channel within tile)
    const int wcol = (tid & 3) * 4;     // 0,4,8,12 (k within tile)
    const int xrow = tid >> 4;          // 0..15  (k within tile)
    const int xcol = (tid & 15) * 4;    // 0..60  (n within tile)

    float acc[4][4] = {};

    for (int c0 = 0; c0 < CCH; c0 += 16) {
        float4 wv4 = *(const float4*)&W[(o0 + wrow) * CCH + c0 + wcol];
        float4 xv4 = *(const float4*)&x[(c0 + xrow) * NTOK + n0 + xcol];
        __syncthreads();
        Ws[wcol + 0][wrow] = wv4.x;
        Ws[wcol + 1][wrow] = wv4.y;
        Ws[wcol + 2][wrow] = wv4.z;
        Ws[wcol + 3][wrow] = wv4.w;
        *(float4*)&Xs[xrow][xcol] = xv4;
        __syncthreads();
        #pragma unroll
        for (int k = 0; k < 16; k++) {
            float a[4], bb[4];
            *(float4*)a  = *(const float4*)&Ws[k][to];
            *(float4*)bb = *(const float4*)&Xs[k][tn];
            #pragma unroll
            for (int i = 0; i < 4; i++)
                #pragma unroll
                for (int j = 0; j < 4; j++)
                    acc[i][j] += a[i] * bb[j];
        }
    }

    #pragma unroll
    for (int i = 0; i < 4; i++) {
        int o = o0 + to + i;
        float bias = b[o];
        int hbase = (o >> 5) << 17;   // head * 4096 * 32
        int dd = o & 31;
        #pragma unroll
        for (int j = 0; j < 4; j++) {
            int n = n0 + tn + j;
            outp[hbase + n * 32 + dd] = acc[i][j] + bias;
        }
    }
}

// ---------------------------------------------------------------------------
// Flash attention (fp32): one query per thread.
// Grid: (32, 8) -> 32 query-blocks of 128 per head, 8 heads. Block: 128 thr.
// ---------------------------------------------------------------------------
__global__ void __launch_bounds__(128) attn_kernel()
{
    const int h   = blockIdx.y;
    const int n   = blockIdx.x * 128 + threadIdx.x;   // query index
    const int tid = threadIdx.x;

    const float* __restrict__ qh = g_q + (h << 17);
    const float* __restrict__ kh = g_k + (h << 17);
    const float* __restrict__ vh = g_v + (h << 17);

    __shared__ float Ks[64 * 32];
    __shared__ float Vs[64 * 32];

    const float scale = 0.17677669529663687f;   // 1/sqrt(32)

    float q[32];
    {
        const float4* qp = (const float4*)(qh + n * 32);
        #pragma unroll
        for (int t = 0; t < 8; t++) {
            float4 v4 = qp[t];
            q[4 * t + 0] = v4.x * scale;
            q[4 * t + 1] = v4.y * scale;
            q[4 * t + 2] = v4.z * scale;
            q[4 * t + 3] = v4.w * scale;
        }
    }

    float o[32];
    #pragma unroll
    for (int t = 0; t < 32; t++) o[t] = 0.0f;
    float m = -1e30f;
    float l = 0.0f;

    for (int kt = 0; kt < NTOK / 64; kt++) {
        __syncthreads();
        // cooperative load of 64 keys + 64 values (2048 floats each)
        const float4* ksrc = (const float4*)(kh + kt * 64 * 32);
        const float4* vsrc = (const float4*)(vh + kt * 64 * 32);
        float4* kdst = (float4*)Ks;
        float4* vdst = (float4*)Vs;
        #pragma unroll
        for (int t = 0; t < 4; t++) {
            kdst[tid + t * 128] = ksrc[tid + t * 128];
            vdst[tid + t * 128] = vsrc[tid + t * 128];
        }
        __syncthreads();

        #pragma unroll
        for (int chunk = 0; chunk < 4; chunk++) {
            const int base = chunk * 16;
            float s[16];
            #pragma unroll
            for (int j = 0; j < 16; j++) {
                const float4* kp = (const float4*)(Ks + (base + j) * 32);
                float acc = 0.0f;
                #pragma unroll
                for (int t = 0; t < 8; t++) {
                    float4 kk = kp[t];
                    acc += q[4 * t + 0] * kk.x;
                    acc += q[4 * t + 1] * kk.y;
                    acc += q[4 * t + 2] * kk.z;
                    acc += q[4 * t + 3] * kk.w;
                }
                s[j] = acc;
            }
            float mnew = m;
            #pragma unroll
            for (int j = 0; j < 16; j++) mnew = fmaxf(mnew, s[j]);
            float alpha = __expf(m - mnew);
            m = mnew;
            l *= alpha;
            #pragma unroll
            for (int t = 0; t < 32; t++) o[t] *= alpha;
            #pragma unroll
            for (int j = 0; j < 16; j++) {
                float p = __expf(s[j] - m);
                l += p;
                const float4* vp = (const float4*)(Vs + (base + j) * 32);
                #pragma unroll
                for (int t = 0; t < 8; t++) {
                    float4 vv = vp[t];
                    o[4 * t + 0] += p * vv.x;
                    o[4 * t + 1] += p * vv.y;
                    o[4 * t + 2] += p * vv.z;
                    o[4 * t + 3] += p * vv.w;
                }
            }
        }
    }

    const float inv = 1.0f / l;
    // store as [c][n] layout: g_attn[(h*32+dd)*4096 + n]
    #pragma unroll
    for (int dd = 0; dd < 32; dd++) {
        g_attn[((h << 5) + dd) * NTOK + n] = o[dd] * inv;
    }
}

// ---------------------------------------------------------------------------
// O projection + residual:
// out[o][n] = x[o][n] + gamma * (sum_c Wo[o][c]*attn[c][n] + bo[o])
// ---------------------------------------------------------------------------
__global__ void __launch_bounds__(256) proj_o_kernel(
    const float* __restrict__ x,
    const float* __restrict__ Wo, const float* __restrict__ bo,
    const float* __restrict__ gamma,
    float* __restrict__ out)
{
    __shared__ float Ws[16][64];
    __shared__ float Xs[16][64];

    const int tid = threadIdx.x;
    const int o0 = blockIdx.y * 64;
    const int n0 = blockIdx.x * 64;
    const int to = (tid >> 4) * 4;
    const int tn = (tid & 15) * 4;

    const int wrow = tid >> 2;
    const int wcol = (tid & 3) * 4;
    const int xrow = tid >> 4;
    const int xcol = (tid & 15) * 4;

    float acc[4][4] = {};

    for (int c0 = 0; c0 < CCH; c0 += 16) {
        float4 wv4 = *(const float4*)&Wo[(o0 + wrow) * CCH + c0 + wcol];
        float4 xv4 = *(const float4*)&g_attn[(c0 + xrow) * NTOK + n0 + xcol];
        __syncthreads();
        Ws[wcol + 0][wrow] = wv4.x;
        Ws[wcol + 1][wrow] = wv4.y;
        Ws[wcol + 2][wrow] = wv4.z;
        Ws[wcol + 3][wrow] = wv4.w;
        *(float4*)&Xs[xrow][xcol] = xv4;
        __syncthreads();
        #pragma unroll
        for (int k = 0; k < 16; k++) {
            float a[4], bb[4];
            *(float4*)a  = *(const float4*)&Ws[k][to];
            *(float4*)bb = *(const float4*)&Xs[k][tn];
            #pragma unroll
            for (int i = 0; i < 4; i++)
                #pragma unroll
                for (int j = 0; j < 4; j++)
                    acc[i][j] += a[i] * bb[j];
        }
    }

    const float g = gamma[0];
    #pragma unroll
    for (int i = 0; i < 4; i++) {
        int o = o0 + to + i;
        float bias = bo[o];
        #pragma unroll
        for (int j = 0; j < 4; j++) {
            int n = n0 + tn + j;
            out[o * NTOK + n] = x[o * NTOK + n] + g * (acc[i][j] + bias);
        }
    }
}

// ---------------------------------------------------------------------------
// Launch
// inputs: x, Wq, bq, Wk, bk, Wv, bv, Wo, bo, gamma
// ---------------------------------------------------------------------------
extern "C" void kernel_launch(void* const* d_in, const int* in_sizes, int n_in,
                              void* d_out, int out_size)
{
    const float* x     = (const float*)d_in[0];
    const float* Wq    = (const float*)d_in[1];
    const float* bq    = (const float*)d_in[2];
    const float* Wk    = (const float*)d_in[3];
    const float* bk    = (const float*)d_in[4];
    const float* Wv    = (const float*)d_in[5];
    const float* bv    = (const float*)d_in[6];
    const float* Wo    = (const float*)d_in[7];
    const float* bo    = (const float*)d_in[8];
    const float* gamma = (const float*)d_in[9];
    float* out = (float*)d_out;

    dim3 projGrid(NTOK / 64, CCH / 64, 3);
    proj_qkv_kernel<<<projGrid, 256>>>(x, Wq, bq, Wk, bk, Wv, bv);

    dim3 attnGrid(NTOK / 128, NHEAD, 1);
    attn_kernel<<<attnGrid, 128>>>();

    dim3 oGrid(NTOK / 64, CCH / 64, 1);
    proj_o_kernel<<<oGrid, 256>>>(x, Wo, bo, gamma, out);
}

// round 3
// speedup vs baseline: 3.6110x; 3.6110x over previous
#include <cuda_runtime.h>
#include <cuda_bf16.h>
#include <cstdint>

// Problem constants: B=1, C=256, N=16*16*16=4096, heads=8, d=32
#define NTOK 4096
#define CCH  256
#define NHEAD 8
#define HDIM 32

// Scratch (device globals; no allocation allowed)
// q,k,v stored bf16 as [head][n][d] : h*131072 + n*32 + dd  (q pre-scaled by 1/sqrt(d))
__device__ __nv_bfloat16 g_qb[NHEAD * NTOK * HDIM];
__device__ __nv_bfloat16 g_kb[NHEAD * NTOK * HDIM];
__device__ __nv_bfloat16 g_vb[NHEAD * NTOK * HDIM];
// attn output stored as [c][n] (same layout as x) for the O projection
__device__ float g_attn[CCH * NTOK];

// ---------------------------------------------------------------------------
// QKV projection: y[o][n] = sum_c W[o][c] * x[c][n] + b[o]  -> bf16 [h][n][d]
// q additionally scaled by 1/sqrt(32).
// ---------------------------------------------------------------------------
__global__ void __launch_bounds__(256) proj_qkv_kernel(
    const float* __restrict__ x,
    const float* __restrict__ Wq, const float* __restrict__ bq,
    const float* __restrict__ Wk, const float* __restrict__ bk,
    const float* __restrict__ Wv, const float* __restrict__ bv)
{
    const float* W; const float* b; __nv_bfloat16* outp; float oscale;
    if (blockIdx.z == 0)      { W = Wq; b = bq; outp = g_qb; oscale = 0.17677669529663687f; }
    else if (blockIdx.z == 1) { W = Wk; b = bk; outp = g_kb; oscale = 1.0f; }
    else                      { W = Wv; b = bv; outp = g_vb; oscale = 1.0f; }

    __shared__ float Ws[16][64];   // [k][o]
    __shared__ float Xs[16][64];   // [k][n]

    const int tid = threadIdx.x;
    const int o0 = blockIdx.y * 64;
    const int n0 = blockIdx.x * 64;
    const int to = (tid >> 4) * 4;
    const int tn = (tid & 15) * 4;

    const int wrow = tid >> 2;
    const int wcol = (tid & 3) * 4;
    const int xrow = tid >> 4;
    const int xcol = (tid & 15) * 4;

    float acc[4][4] = {};

    for (int c0 = 0; c0 < CCH; c0 += 16) {
        float4 wv4 = *(const float4*)&W[(o0 + wrow) * CCH + c0 + wcol];
        float4 xv4 = *(const float4*)&x[(c0 + xrow) * NTOK + n0 + xcol];
        __syncthreads();
        Ws[wcol + 0][wrow] = wv4.x;
        Ws[wcol + 1][wrow] = wv4.y;
        Ws[wcol + 2][wrow] = wv4.z;
        Ws[wcol + 3][wrow] = wv4.w;
        *(float4*)&Xs[xrow][xcol] = xv4;
        __syncthreads();
        #pragma unroll
        for (int k = 0; k < 16; k++) {
            float a[4], bb[4];
            *(float4*)a  = *(const float4*)&Ws[k][to];
            *(float4*)bb = *(const float4*)&Xs[k][tn];
            #pragma unroll
            for (int i = 0; i < 4; i++)
                #pragma unroll
                for (int j = 0; j < 4; j++)
                    acc[i][j] += a[i] * bb[j];
        }
    }

    #pragma unroll
    for (int i = 0; i < 4; i++) {
        int o = o0 + to + i;
        float bias = b[o];
        int hbase = (o >> 5) << 17;   // head * 4096 * 32
        int dd = o & 31;
        #pragma unroll
        for (int j = 0; j < 4; j++) {
            int n = n0 + tn + j;
            outp[hbase + n * 32 + dd] = __float2bfloat16((acc[i][j] + bias) * oscale);
        }
    }
}

// ---------------------------------------------------------------------------
// Flash attention with mma.sync bf16 (fp32 accumulate).
// CTA: 128 queries of one head, 8 warps x 16 query rows. K tiles of 64.
// ---------------------------------------------------------------------------
#define TQ 128
#define TK 64
#define PADS 40   // padded bf16 row stride (conflict-free ldmatrix)

__device__ __forceinline__ uint32_t sptr(const void* p) {
    return (uint32_t)__cvta_generic_to_shared(p);
}

__device__ __forceinline__ void ldm_x4(uint32_t& r0, uint32_t& r1, uint32_t& r2, uint32_t& r3, uint32_t addr) {
    asm volatile("ldmatrix.sync.aligned.m8n8.x4.shared.b16 {%0,%1,%2,%3}, [%4];"
                 : "=r"(r0), "=r"(r1), "=r"(r2), "=r"(r3) : "r"(addr));
}
__device__ __forceinline__ void ldm_x4t(uint32_t& r0, uint32_t& r1, uint32_t& r2, uint32_t& r3, uint32_t addr) {
    asm volatile("ldmatrix.sync.aligned.m8n8.x4.trans.shared.b16 {%0,%1,%2,%3}, [%4];"
                 : "=r"(r0), "=r"(r1), "=r"(r2), "=r"(r3) : "r"(addr));
}
__device__ __forceinline__ void mma_bf16(float* c, uint32_t a0, uint32_t a1, uint32_t a2, uint32_t a3,
                                         uint32_t b0, uint32_t b1) {
    asm volatile("mma.sync.aligned.m16n8k16.row.col.f32.bf16.bf16.f32 "
                 "{%0,%1,%2,%3}, {%4,%5,%6,%7}, {%8,%9}, {%0,%1,%2,%3};"
                 : "+f"(c[0]), "+f"(c[1]), "+f"(c[2]), "+f"(c[3])
                 : "r"(a0), "r"(a1), "r"(a2), "r"(a3), "r"(b0), "r"(b1));
}
__device__ __forceinline__ uint32_t pack_bf16x2(float hi, float lo) {
    uint32_t d;
    asm volatile("cvt.rn.bf16x2.f32 %0, %1, %2;" : "=r"(d) : "f"(hi), "f"(lo));
    return d;
}

__global__ void __launch_bounds__(256) attn_mma_kernel()
{
    const int h   = blockIdx.y;
    const int q0  = blockIdx.x * TQ;
    const int tid = threadIdx.x;
    const int wid = tid >> 5;
    const int lane = tid & 31;

    const __nv_bfloat16* __restrict__ qh = g_qb + (h << 17);
    const __nv_bfloat16* __restrict__ kh = g_kb + (h << 17);
    const __nv_bfloat16* __restrict__ vh = g_vb + (h << 17);

    __shared__ __nv_bfloat16 Qs[TQ * PADS];
    __shared__ __nv_bfloat16 Ks[TK * PADS];
    __shared__ __nv_bfloat16 Vs[TK * PADS];

    // ---- load Q tile (128 rows x 32 bf16; 4 uint4 per row) ----
    {
        const uint4* qsrc = (const uint4*)(qh + q0 * HDIM);
        #pragma unroll
        for (int t = 0; t < 2; t++) {
            int idx = tid + t * 256;             // 0..511
            int row = idx >> 2, ch = idx & 3;
            uint4 v = qsrc[idx];
            *(uint4*)((char*)Qs + row * (PADS * 2) + ch * 16) = v;
        }
    }
    __syncthreads();

    // ---- Q A-fragments (constant for all tiles): qa[kstep][4] ----
    uint32_t qa[2][4];
    {
        const uint32_t qbase = sptr(Qs);
        #pragma unroll
        for (int ks = 0; ks < 2; ks++) {
            int row = wid * 16 + (lane & 15);
            int col = (lane >> 4) * 8 + ks * 16;
            uint32_t addr = qbase + (uint32_t)(row * PADS + col) * 2;
            ldm_x4(qa[ks][0], qa[ks][1], qa[ks][2], qa[ks][3], addr);
        }
    }

    const uint32_t ksb = sptr(Ks);
    const uint32_t vsb = sptr(Vs);

    float o_[4][4];
    #pragma unroll
    for (int i = 0; i < 4; i++)
        #pragma unroll
        for (int j = 0; j < 4; j++) o_[i][j] = 0.0f;
    float m0 = -1e30f, m1 = -1e30f, l0 = 0.0f, l1 = 0.0f;

    // prefetch tile 0
    const int prow = tid >> 2, pch = tid & 3;
    uint4 kreg = ((const uint4*)kh)[prow * 4 + pch];
    uint4 vreg = ((const uint4*)vh)[prow * 4 + pch];

    for (int kt = 0; kt < NTOK / TK; kt++) {
        __syncthreads();   // previous tile fully consumed
        *(uint4*)((char*)Ks + prow * (PADS * 2) + pch * 16) = kreg;
        *(uint4*)((char*)Vs + prow * (PADS * 2) + pch * 16) = vreg;
        __syncthreads();
        if (kt + 1 < NTOK / TK) {
            int base = (kt + 1) * TK;
            kreg = ((const uint4*)kh)[(base + prow) * 4 + pch];
            vreg = ((const uint4*)vh)[(base + prow) * 4 + pch];
        }

        // ---- S = Q K^T  (8 n-tiles of 8 keys) ----
        float s[8][4];
        #pragma unroll
        for (int j = 0; j < 8; j++) {
            s[j][0] = s[j][1] = s[j][2] = s[j][3] = 0.0f;
            uint32_t k0, k1, k2, k3;
            uint32_t addr = ksb + (uint32_t)((8 * j + (lane & 7)) * PADS + (lane >> 3) * 8) * 2;
            ldm_x4(k0, k1, k2, k3, addr);
            mma_bf16(s[j], qa[0][0], qa[0][1], qa[0][2], qa[0][3], k0, k1);
            mma_bf16(s[j], qa[1][0], qa[1][1], qa[1][2], qa[1][3], k2, k3);
        }

        // ---- online softmax (rows r0=lane/4, r1=r0+8) ----
        float tm0 = -1e30f, tm1 = -1e30f;
        #pragma unroll
        for (int j = 0; j < 8; j++) {
            tm0 = fmaxf(tm0, fmaxf(s[j][0], s[j][1]));
            tm1 = fmaxf(tm1, fmaxf(s[j][2], s[j][3]));
        }
        tm0 = fmaxf(tm0, __shfl_xor_sync(0xffffffffu, tm0, 1));
        tm0 = fmaxf(tm0, __shfl_xor_sync(0xffffffffu, tm0, 2));
        tm1 = fmaxf(tm1, __shfl_xor_sync(0xffffffffu, tm1, 1));
        tm1 = fmaxf(tm1, __shfl_xor_sync(0xffffffffu, tm1, 2));

        float mn0 = fmaxf(m0, tm0);
        float mn1 = fmaxf(m1, tm1);
        float al0 = __expf(m0 - mn0);
        float al1 = __expf(m1 - mn1);
        m0 = mn0; m1 = mn1;
        l0 *= al0; l1 *= al1;
        #pragma unroll
        for (int t = 0; t < 4; t++) {
            o_[t][0] *= al0; o_[t][1] *= al0;
            o_[t][2] *= al1; o_[t][3] *= al1;
        }

        uint32_t pa[8][2];
        #pragma unroll
        for (int j = 0; j < 8; j++) {
            float p0 = __expf(s[j][0] - m0);
            float p1 = __expf(s[j][1] - m0);
            float p2 = __expf(s[j][2] - m1);
            float p3 = __expf(s[j][3] - m1);
            l0 += p0 + p1;
            l1 += p2 + p3;
            pa[j][0] = pack_bf16x2(p1, p0);   // lo = even col
            pa[j][1] = pack_bf16x2(p3, p2);
        }

        // ---- O += P V  (4 k-chunks of 16 keys, 4 d-tiles) ----
        #pragma unroll
        for (int c = 0; c < 4; c++) {
            uint32_t vb[8];
            uint32_t keyrow = 16 * c + (lane & 7) + ((lane & 8) ? 8 : 0);
            uint32_t dofs   = (lane & 16) ? 8 : 0;
            uint32_t addrA  = vsb + (uint32_t)(keyrow * PADS + dofs) * 2;
            ldm_x4t(vb[0], vb[1], vb[2], vb[3], addrA);
            ldm_x4t(vb[4], vb[5], vb[6], vb[7], addrA + 32);   // d + 16
            #pragma unroll
            for (int dt = 0; dt < 4; dt++) {
                mma_bf16(o_[dt], pa[2 * c][0], pa[2 * c][1], pa[2 * c + 1][0], pa[2 * c + 1][1],
                         vb[2 * dt], vb[2 * dt + 1]);
            }
        }
    }

    // ---- finalize ----
    l0 += __shfl_xor_sync(0xffffffffu, l0, 1);
    l0 += __shfl_xor_sync(0xffffffffu, l0, 2);
    l1 += __shfl_xor_sync(0xffffffffu, l1, 1);
    l1 += __shfl_xor_sync(0xffffffffu, l1, 2);
    const float inv0 = 1.0f / l0;
    const float inv1 = 1.0f / l1;

    const int r0 = q0 + wid * 16 + (lane >> 2);
    const int r1 = r0 + 8;
    const int cbase = h * 32 + 2 * (lane & 3);
    #pragma unroll
    for (int dt = 0; dt < 4; dt++) {
        int c = cbase + dt * 8;
        g_attn[(c + 0) * NTOK + r0] = o_[dt][0] * inv0;
        g_attn[(c + 1) * NTOK + r0] = o_[dt][1] * inv0;
        g_attn[(c + 0) * NTOK + r1] = o_[dt][2] * inv1;
        g_attn[(c + 1) * NTOK + r1] = o_[dt][3] * inv1;
    }
}

// ---------------------------------------------------------------------------
// O projection + residual:
// out[o][n] = x[o][n] + gamma * (sum_c Wo[o][c]*attn[c][n] + bo[o])
// ---------------------------------------------------------------------------
__global__ void __launch_bounds__(256) proj_o_kernel(
    const float* __restrict__ x,
    const float* __restrict__ Wo, const float* __restrict__ bo,
    const float* __restrict__ gamma,
    float* __restrict__ out)
{
    __shared__ float Ws[16][64];
    __shared__ float Xs[16][64];

    const int tid = threadIdx.x;
    const int o0 = blockIdx.y * 64;
    const int n0 = blockIdx.x * 64;
    const int to = (tid >> 4) * 4;
    const int tn = (tid & 15) * 4;

    const int wrow = tid >> 2;
    const int wcol = (tid & 3) * 4;
    const int xrow = tid >> 4;
    const int xcol = (tid & 15) * 4;

    float acc[4][4] = {};

    for (int c0 = 0; c0 < CCH; c0 += 16) {
        float4 wv4 = *(const float4*)&Wo[(o0 + wrow) * CCH + c0 + wcol];
        float4 xv4 = *(const float4*)&g_attn[(c0 + xrow) * NTOK + n0 + xcol];
        __syncthreads();
        Ws[wcol + 0][wrow] = wv4.x;
        Ws[wcol + 1][wrow] = wv4.y;
        Ws[wcol + 2][wrow] = wv4.z;
        Ws[wcol + 3][wrow] = wv4.w;
        *(float4*)&Xs[xrow][xcol] = xv4;
        __syncthreads();
        #pragma unroll
        for (int k = 0; k < 16; k++) {
            float a[4], bb[4];
            *(float4*)a  = *(const float4*)&Ws[k][to];
            *(float4*)bb = *(const float4*)&Xs[k][tn];
            #pragma unroll
            for (int i = 0; i < 4; i++)
                #pragma unroll
                for (int j = 0; j < 4; j++)
                    acc[i][j] += a[i] * bb[j];
        }
    }

    const float g = gamma[0];
    #pragma unroll
    for (int i = 0; i < 4; i++) {
        int o = o0 + to + i;
        float bias = bo[o];
        #pragma unroll
        for (int j = 0; j < 4; j++) {
            int n = n0 + tn + j;
            out[o * NTOK + n] = x[o * NTOK + n] + g * (acc[i][j] + bias);
        }
    }
}

// ---------------------------------------------------------------------------
// Launch: inputs x, Wq, bq, Wk, bk, Wv, bv, Wo, bo, gamma
// ---------------------------------------------------------------------------
extern "C" void kernel_launch(void* const* d_in, const int* in_sizes, int n_in,
                              void* d_out, int out_size)
{
    const float* x     = (const float*)d_in[0];
    const float* Wq    = (const float*)d_in[1];
    const float* bq    = (const float*)d_in[2];
    const float* Wk    = (const float*)d_in[3];
    const float* bk    = (const float*)d_in[4];
    const float* Wv    = (const float*)d_in[5];
    const float* bv    = (const float*)d_in[6];
    const float* Wo    = (const float*)d_in[7];
    const float* bo    = (const float*)d_in[8];
    const float* gamma = (const float*)d_in[9];
    float* out = (float*)d_out;

    dim3 projGrid(NTOK / 64, CCH / 64, 3);
    proj_qkv_kernel<<<projGrid, 256>>>(x, Wq, bq, Wk, bk, Wv, bv);

    dim3 attnGrid(NTOK / TQ, NHEAD, 1);
    attn_mma_kernel<<<attnGrid, 256>>>();

    dim3 oGrid(NTOK / 64, CCH / 64, 1);
    proj_o_kernel<<<oGrid, 256>>>(x, Wo, bo, gamma, out);
}

// round 4
// speedup vs baseline: 6.1091x; 1.6918x over previous
#include <cuda_runtime.h>
#include <cuda_bf16.h>
#include <cstdint>

// Problem constants: B=1, C=256, N=16*16*16=4096, heads=8, d=32
#define NTOK 4096
#define CCH  256
#define NHEAD 8
#define HDIM 32

// log2(e)/sqrt(32): folded into q so softmax uses ex2 directly
#define QSCALE 0.25503482617f

// ---------------- device scratch (no allocation allowed) ----------------
__device__ __nv_bfloat16 g_xb[CCH * NTOK];          // x bf16, [c][n]
__device__ __nv_bfloat16 g_Wb[4 * CCH * CCH];       // Wq|Wk|Wv|Wo bf16
__device__ __nv_bfloat16 g_qb[NHEAD * NTOK * HDIM]; // [h][n][d], pre-scaled by QSCALE
__device__ __nv_bfloat16 g_kb[NHEAD * NTOK * HDIM];
__device__ __nv_bfloat16 g_vb[NHEAD * NTOK * HDIM];
__device__ __nv_bfloat16 g_attnb[NTOK * CCH];       // [n][c]

// ---------------- helpers ----------------
__device__ __forceinline__ uint32_t sptr(const void* p) {
    return (uint32_t)__cvta_generic_to_shared(p);
}
__device__ __forceinline__ void ldm_x4(uint32_t& r0, uint32_t& r1, uint32_t& r2, uint32_t& r3, uint32_t addr) {
    asm volatile("ldmatrix.sync.aligned.m8n8.x4.shared.b16 {%0,%1,%2,%3}, [%4];"
                 : "=r"(r0), "=r"(r1), "=r"(r2), "=r"(r3) : "r"(addr));
}
__device__ __forceinline__ void ldm_x4t(uint32_t& r0, uint32_t& r1, uint32_t& r2, uint32_t& r3, uint32_t addr) {
    asm volatile("ldmatrix.sync.aligned.m8n8.x4.trans.shared.b16 {%0,%1,%2,%3}, [%4];"
                 : "=r"(r0), "=r"(r1), "=r"(r2), "=r"(r3) : "r"(addr));
}
__device__ __forceinline__ void mma_bf16(float* c, uint32_t a0, uint32_t a1, uint32_t a2, uint32_t a3,
                                         uint32_t b0, uint32_t b1) {
    asm volatile("mma.sync.aligned.m16n8k16.row.col.f32.bf16.bf16.f32 "
                 "{%0,%1,%2,%3}, {%4,%5,%6,%7}, {%8,%9}, {%0,%1,%2,%3};"
                 : "+f"(c[0]), "+f"(c[1]), "+f"(c[2]), "+f"(c[3])
                 : "r"(a0), "r"(a1), "r"(a2), "r"(a3), "r"(b0), "r"(b1));
}
__device__ __forceinline__ uint32_t pack_bf16x2(float hi, float lo) {
    uint32_t d;
    asm volatile("cvt.rn.bf16x2.f32 %0, %1, %2;" : "=r"(d) : "f"(hi), "f"(lo));
    return d;
}
__device__ __forceinline__ float ex2f(float x) {
    float y;
    asm volatile("ex2.approx.f32 %0, %1;" : "=f"(y) : "f"(x));
    return y;
}

// ---------------------------------------------------------------------------
// Convert x + 4 weight matrices fp32 -> bf16.
// total float4s: 262144 (x) + 4*16384 (W) = 327680 -> 1280 blocks x 256 thr
// ---------------------------------------------------------------------------
__global__ void __launch_bounds__(256) convert_kernel(
    const float* __restrict__ x,
    const float* __restrict__ Wq, const float* __restrict__ Wk,
    const float* __restrict__ Wv, const float* __restrict__ Wo)
{
    int i4 = blockIdx.x * 256 + threadIdx.x;
    const float* src;
    __nv_bfloat16* dst;
    int off4;
    if (i4 < 262144) { src = x; dst = g_xb; off4 = i4; }
    else {
        int j = i4 - 262144;
        int r = j >> 14;
        off4 = j & 16383;
        src = (r == 0) ? Wq : (r == 1) ? Wk : (r == 2) ? Wv : Wo;
        dst = g_Wb + r * (CCH * CCH);
    }
    float4 v = ((const float4*)src)[off4];
    __nv_bfloat162 lo = __floats2bfloat162_rn(v.x, v.y);
    __nv_bfloat162 hi = __floats2bfloat162_rn(v.z, v.w);
    uint2 pk;
    pk.x = *(uint32_t*)&lo;
    pk.y = *(uint32_t*)&hi;
    *(uint2*)&dst[off4 * 4] = pk;
}

// ---------------------------------------------------------------------------
// QKV projection with bf16 mma: out[o][n] = sum_c W[o][c] * x[c][n] + b[o]
// CTA tile 128(m) x 128(n), K staged in 32-chunks. 8 warps as 4(m) x 2(n),
// warp tile 32x64. Output bf16 into [h][n][d]; q scaled by QSCALE.
// ---------------------------------------------------------------------------
__global__ void __launch_bounds__(256) gemm_qkv_kernel(
    const float* __restrict__ bq, const float* __restrict__ bk, const float* __restrict__ bv)
{
    const __nv_bfloat16* W; const float* bias; __nv_bfloat16* outp; float sc;
    if (blockIdx.z == 0)      { W = g_Wb;               bias = bq; outp = g_qb; sc = QSCALE; }
    else if (blockIdx.z == 1) { W = g_Wb + CCH * CCH;   bias = bk; outp = g_kb; sc = 1.0f; }
    else                      { W = g_Wb + 2 * CCH * CCH; bias = bv; outp = g_vb; sc = 1.0f; }

    __shared__ __nv_bfloat16 As[128 * 40];   // [m][k], pad->40
    __shared__ __nv_bfloat16 Bs[32 * 136];   // [k][n], pad->136

    const int tid  = threadIdx.x;
    const int lane = tid & 31;
    const int wid  = tid >> 5;
    const int wm   = wid & 3;     // m quadrant (32 rows)
    const int wn   = wid >> 2;    // n half (64 cols)
    const int o0   = blockIdx.y * 128;
    const int n0   = blockIdx.x * 128;

    const int arow = tid >> 2, ac4 = tid & 3;    // A: rows arow, arow+64; 16B chunk ac4
    const int brow = tid >> 4, bc4 = tid & 15;   // B: rows brow, brow+16

    uint4 pa0, pa1, pb0, pb1;
    {
        pa0 = *(const uint4*)&W[(o0 + arow) * CCH + ac4 * 8];
        pa1 = *(const uint4*)&W[(o0 + arow + 64) * CCH + ac4 * 8];
        pb0 = *(const uint4*)&g_xb[(brow) * NTOK + n0 + bc4 * 8];
        pb1 = *(const uint4*)&g_xb[(brow + 16) * NTOK + n0 + bc4 * 8];
    }

    float acc[2][8][4];
    #pragma unroll
    for (int i = 0; i < 2; i++)
        #pragma unroll
        for (int j = 0; j < 8; j++)
            #pragma unroll
            for (int r = 0; r < 4; r++) acc[i][j][r] = 0.0f;

    const uint32_t asb = sptr(As);
    const uint32_t bsb = sptr(Bs);

    for (int s = 0; s < 8; s++) {
        __syncthreads();
        *(uint4*)&As[arow * 40 + ac4 * 8] = pa0;
        *(uint4*)&As[(arow + 64) * 40 + ac4 * 8] = pa1;
        *(uint4*)&Bs[brow * 136 + bc4 * 8] = pb0;
        *(uint4*)&Bs[(brow + 16) * 136 + bc4 * 8] = pb1;
        __syncthreads();
        if (s < 7) {
            int k0 = (s + 1) * 32;
            pa0 = *(const uint4*)&W[(o0 + arow) * CCH + k0 + ac4 * 8];
            pa1 = *(const uint4*)&W[(o0 + arow + 64) * CCH + k0 + ac4 * 8];
            pb0 = *(const uint4*)&g_xb[(k0 + brow) * NTOK + n0 + bc4 * 8];
            pb1 = *(const uint4*)&g_xb[(k0 + brow + 16) * NTOK + n0 + bc4 * 8];
        }
        #pragma unroll
        for (int ks = 0; ks < 2; ks++) {
            uint32_t a[2][4];
            #pragma unroll
            for (int mi = 0; mi < 2; mi++) {
                int row = wm * 32 + mi * 16 + (lane & 15);
                int col = (lane >> 4) * 8 + ks * 16;
                ldm_x4(a[mi][0], a[mi][1], a[mi][2], a[mi][3], asb + (uint32_t)(row * 40 + col) * 2);
            }
            uint32_t b[4][4];
            #pragma unroll
            for (int nq = 0; nq < 4; nq++) {
                int krow = ks * 16 + (lane & 7) + ((lane & 8) ? 8 : 0);
                int ncol = wn * 64 + nq * 16 + ((lane & 16) ? 8 : 0);
                ldm_x4t(b[nq][0], b[nq][1], b[nq][2], b[nq][3], bsb + (uint32_t)(krow * 136 + ncol) * 2);
            }
            #pragma unroll
            for (int mi = 0; mi < 2; mi++)
                #pragma unroll
                for (int nj = 0; nj < 8; nj++) {
                    int nq = nj >> 1, sel = nj & 1;
                    mma_bf16(acc[mi][nj], a[mi][0], a[mi][1], a[mi][2], a[mi][3],
                             b[nq][2 * sel], b[nq][2 * sel + 1]);
                }
        }
    }

    // epilogue: bias + scale, write bf16 [h][n][d]
    float bz[2][2];
    #pragma unroll
    for (int mi = 0; mi < 2; mi++)
        #pragma unroll
        for (int hh = 0; hh < 2; hh++)
            bz[mi][hh] = bias[o0 + wm * 32 + mi * 16 + (lane >> 2) + 8 * hh];

    #pragma unroll
    for (int mi = 0; mi < 2; mi++)
        #pragma unroll
        for (int nj = 0; nj < 8; nj++)
            #pragma unroll
            for (int r = 0; r < 4; r++) {
                int m = o0 + wm * 32 + mi * 16 + (lane >> 2) + (r >> 1) * 8;
                int n = n0 + wn * 64 + nj * 8 + 2 * (lane & 3) + (r & 1);
                float v = (acc[mi][nj][r] + bz[mi][r >> 1]) * sc;
                outp[((m >> 5) << 17) + n * HDIM + (m & 31)] = __float2bfloat16(v);
            }
}

// ---------------------------------------------------------------------------
// Flash attention, bf16 mma, NO max subtraction (scores bounded), ex2 softmax.
// CTA: 128 queries x one head, 8 warps x 16 rows, K/V tiles of 64.
// Output bf16 [n][c].
// ---------------------------------------------------------------------------
#define TQ 128
#define TK 64
#define PADS 40

__global__ void __launch_bounds__(256) attn_mma_kernel()
{
    const int h    = blockIdx.y;
    const int q0   = blockIdx.x * TQ;
    const int tid  = threadIdx.x;
    const int wid  = tid >> 5;
    const int lane = tid & 31;

    const __nv_bfloat16* __restrict__ qh = g_qb + (h << 17);
    const __nv_bfloat16* __restrict__ kh = g_kb + (h << 17);
    const __nv_bfloat16* __restrict__ vh = g_vb + (h << 17);

    __shared__ __nv_bfloat16 Qs[TQ * PADS];
    __shared__ __nv_bfloat16 Ks[TK * PADS];
    __shared__ __nv_bfloat16 Vs[TK * PADS];

    // load Q tile (128 x 32 bf16)
    {
        const uint4* qsrc = (const uint4*)(qh + q0 * HDIM);
        #pragma unroll
        for (int t = 0; t < 2; t++) {
            int idx = tid + t * 256;
            int row = idx >> 2, ch = idx & 3;
            *(uint4*)((char*)Qs + row * (PADS * 2) + ch * 16) = qsrc[idx];
        }
    }
    __syncthreads();

    uint32_t qa[2][4];
    {
        const uint32_t qbase = sptr(Qs);
        #pragma unroll
        for (int ks = 0; ks < 2; ks++) {
            int row = wid * 16 + (lane & 15);
            int col = (lane >> 4) * 8 + ks * 16;
            ldm_x4(qa[ks][0], qa[ks][1], qa[ks][2], qa[ks][3],
                   qbase + (uint32_t)(row * PADS + col) * 2);
        }
    }

    const uint32_t ksb = sptr(Ks);
    const uint32_t vsb = sptr(Vs);

    float o_[4][4];
    #pragma unroll
    for (int i = 0; i < 4; i++)
        #pragma unroll
        for (int j = 0; j < 4; j++) o_[i][j] = 0.0f;
    float l0 = 0.0f, l1 = 0.0f;

    const int prow = tid >> 2, pch = tid & 3;
    uint4 kreg = ((const uint4*)kh)[prow * 4 + pch];
    uint4 vreg = ((const uint4*)vh)[prow * 4 + pch];

    for (int kt = 0; kt < NTOK / TK; kt++) {
        __syncthreads();
        *(uint4*)((char*)Ks + prow * (PADS * 2) + pch * 16) = kreg;
        *(uint4*)((char*)Vs + prow * (PADS * 2) + pch * 16) = vreg;
        __syncthreads();
        if (kt + 1 < NTOK / TK) {
            int base = (kt + 1) * TK;
            kreg = ((const uint4*)kh)[(base + prow) * 4 + pch];
            vreg = ((const uint4*)vh)[(base + prow) * 4 + pch];
        }

        // S = Q K^T  (q pre-scaled by log2e/sqrt(d))
        float s[8][4];
        #pragma unroll
        for (int j = 0; j < 8; j++) {
            s[j][0] = s[j][1] = s[j][2] = s[j][3] = 0.0f;
            uint32_t k0, k1, k2, k3;
            uint32_t addr = ksb + (uint32_t)((8 * j + (lane & 7)) * PADS + (lane >> 3) * 8) * 2;
            ldm_x4(k0, k1, k2, k3, addr);
            mma_bf16(s[j], qa[0][0], qa[0][1], qa[0][2], qa[0][3], k0, k1);
            mma_bf16(s[j], qa[1][0], qa[1][1], qa[1][2], qa[1][3], k2, k3);
        }

        // p = 2^s, accumulate row sums, pack bf16
        uint32_t pa[8][2];
        #pragma unroll
        for (int j = 0; j < 8; j++) {
            float p0 = ex2f(s[j][0]);
            float p1 = ex2f(s[j][1]);
            float p2 = ex2f(s[j][2]);
            float p3 = ex2f(s[j][3]);
            l0 += p0 + p1;
            l1 += p2 + p3;
            pa[j][0] = pack_bf16x2(p1, p0);
            pa[j][1] = pack_bf16x2(p3, p2);
        }

        // O += P V
        #pragma unroll
        for (int c = 0; c < 4; c++) {
            uint32_t vb[8];
            uint32_t keyrow = 16 * c + (lane & 7) + ((lane & 8) ? 8 : 0);
            uint32_t dofs   = (lane & 16) ? 8 : 0;
            uint32_t addrA  = vsb + (uint32_t)(keyrow * PADS + dofs) * 2;
            ldm_x4t(vb[0], vb[1], vb[2], vb[3], addrA);
            ldm_x4t(vb[4], vb[5], vb[6], vb[7], addrA + 32);
            #pragma unroll
            for (int dt = 0; dt < 4; dt++) {
                mma_bf16(o_[dt], pa[2 * c][0], pa[2 * c][1], pa[2 * c + 1][0], pa[2 * c + 1][1],
                         vb[2 * dt], vb[2 * dt + 1]);
            }
        }
    }

    // finalize
    l0 += __shfl_xor_sync(0xffffffffu, l0, 1);
    l0 += __shfl_xor_sync(0xffffffffu, l0, 2);
    l1 += __shfl_xor_sync(0xffffffffu, l1, 1);
    l1 += __shfl_xor_sync(0xffffffffu, l1, 2);
    const float inv0 = 1.0f / l0;
    const float inv1 = 1.0f / l1;

    const int r0 = q0 + wid * 16 + (lane >> 2);
    const int r1 = r0 + 8;
    const int cbase = h * 32 + 2 * (lane & 3);
    #pragma unroll
    for (int dt = 0; dt < 4; dt++) {
        int c = cbase + dt * 8;
        __nv_bfloat162 v0 = __floats2bfloat162_rn(o_[dt][0] * inv0, o_[dt][1] * inv0);
        __nv_bfloat162 v1 = __floats2bfloat162_rn(o_[dt][2] * inv1, o_[dt][3] * inv1);
        *(uint32_t*)&g_attnb[r0 * CCH + c] = *(uint32_t*)&v0;
        *(uint32_t*)&g_attnb[r1 * CCH + c] = *(uint32_t*)&v1;
    }
}

// ---------------------------------------------------------------------------
// O projection + residual, bf16 mma:
// out[o][n] = x[o][n] + gamma * (sum_c Wo[o][c]*attn[c][n] + bo[o])
// B = g_attnb [n][c] (k-contig rows -> plain ldmatrix).
// ---------------------------------------------------------------------------
__global__ void __launch_bounds__(256) gemm_o_kernel(
    const float* __restrict__ x,
    const float* __restrict__ bo, const float* __restrict__ gamma,
    float* __restrict__ out)
{
    const __nv_bfloat16* W = g_Wb + 3 * CCH * CCH;

    __shared__ __nv_bfloat16 As[128 * 40];   // [m][k]
    __shared__ __nv_bfloat16 Bs[128 * 40];   // [n][k]

    const int tid  = threadIdx.x;
    const int lane = tid & 31;
    const int wid  = tid >> 5;
    const int wm   = wid & 3;
    const int wn   = wid >> 2;
    const int o0   = blockIdx.y * 128;
    const int n0   = blockIdx.x * 128;

    const int arow = tid >> 2, ac4 = tid & 3;

    uint4 pa0, pa1, pb0, pb1;
    {
        pa0 = *(const uint4*)&W[(o0 + arow) * CCH + ac4 * 8];
        pa1 = *(const uint4*)&W[(o0 + arow + 64) * CCH + ac4 * 8];
        pb0 = *(const uint4*)&g_attnb[(n0 + arow) * CCH + ac4 * 8];
        pb1 = *(const uint4*)&g_attnb[(n0 + arow + 64) * CCH + ac4 * 8];
    }

    float acc[2][8][4];
    #pragma unroll
    for (int i = 0; i < 2; i++)
        #pragma unroll
        for (int j = 0; j < 8; j++)
            #pragma unroll
            for (int r = 0; r < 4; r++) acc[i][j][r] = 0.0f;

    const uint32_t asb = sptr(As);
    const uint32_t bsb = sptr(Bs);

    for (int s = 0; s < 8; s++) {
        __syncthreads();
        *(uint4*)&As[arow * 40 + ac4 * 8] = pa0;
        *(uint4*)&As[(arow + 64) * 40 + ac4 * 8] = pa1;
        *(uint4*)&Bs[arow * 40 + ac4 * 8] = pb0;
        *(uint4*)&Bs[(arow + 64) * 40 + ac4 * 8] = pb1;
        __syncthreads();
        if (s < 7) {
            int k0 = (s + 1) * 32;
            pa0 = *(const uint4*)&W[(o0 + arow) * CCH + k0 + ac4 * 8];
            pa1 = *(const uint4*)&W[(o0 + arow + 64) * CCH + k0 + ac4 * 8];
            pb0 = *(const uint4*)&g_attnb[(n0 + arow) * CCH + k0 + ac4 * 8];
            pb1 = *(const uint4*)&g_attnb[(n0 + arow + 64) * CCH + k0 + ac4 * 8];
        }

        // B fragments: one x4 per n-tile covers k 0..31 of this stage
        uint32_t b[8][4];
        #pragma unroll
        for (int nt = 0; nt < 8; nt++) {
            uint32_t addr = bsb + (uint32_t)((wn * 64 + nt * 8 + (lane & 7)) * 40 + (lane >> 3) * 8) * 2;
            ldm_x4(b[nt][0], b[nt][1], b[nt][2], b[nt][3], addr);
        }
        #pragma unroll
        for (int ks = 0; ks < 2; ks++) {
            uint32_t a[2][4];
            #pragma unroll
            for (int mi = 0; mi < 2; mi++) {
                int row = wm * 32 + mi * 16 + (lane & 15);
                int col = (lane >> 4) * 8 + ks * 16;
                ldm_x4(a[mi][0], a[mi][1], a[mi][2], a[mi][3], asb + (uint32_t)(row * 40 + col) * 2);
            }
            #pragma unroll
            for (int mi = 0; mi < 2; mi++)
                #pragma unroll
                for (int nt = 0; nt < 8; nt++)
                    mma_bf16(acc[mi][nt], a[mi][0], a[mi][1], a[mi][2], a[mi][3],
                             b[nt][2 * ks], b[nt][2 * ks + 1]);
        }
    }

    const float g = gamma[0];
    float bz[2][2];
    #pragma unroll
    for (int mi = 0; mi < 2; mi++)
        #pragma unroll
        for (int hh = 0; hh < 2; hh++)
            bz[mi][hh] = bo[o0 + wm * 32 + mi * 16 + (lane >> 2) + 8 * hh];

    #pragma unroll
    for (int mi = 0; mi < 2; mi++)
        #pragma unroll
        for (int nt = 0; nt < 8; nt++) {
            int m = o0 + wm * 32 + mi * 16 + (lane >> 2);
            int n = n0 + wn * 64 + nt * 8 + 2 * (lane & 3);
            {
                float2 xv = *(const float2*)&x[m * NTOK + n];
                float2 ov;
                ov.x = xv.x + g * (acc[mi][nt][0] + bz[mi][0]);
                ov.y = xv.y + g * (acc[mi][nt][1] + bz[mi][0]);
                *(float2*)&out[m * NTOK + n] = ov;
            }
            {
                int m2 = m + 8;
                float2 xv = *(const float2*)&x[m2 * NTOK + n];
                float2 ov;
                ov.x = xv.x + g * (acc[mi][nt][2] + bz[mi][1]);
                ov.y = xv.y + g * (acc[mi][nt][3] + bz[mi][1]);
                *(float2*)&out[m2 * NTOK + n] = ov;
            }
        }
}

// ---------------------------------------------------------------------------
// Launch: inputs x, Wq, bq, Wk, bk, Wv, bv, Wo, bo, gamma
// ---------------------------------------------------------------------------
extern "C" void kernel_launch(void* const* d_in, const int* in_sizes, int n_in,
                              void* d_out, int out_size)
{
    const float* x     = (const float*)d_in[0];
    const float* Wq    = (const float*)d_in[1];
    const float* bq    = (const float*)d_in[2];
    const float* Wk    = (const float*)d_in[3];
    const float* bk    = (const float*)d_in[4];
    const float* Wv    = (const float*)d_in[5];
    const float* bv    = (const float*)d_in[6];
    const float* Wo    = (const float*)d_in[7];
    const float* bo    = (const float*)d_in[8];
    const float* gamma = (const float*)d_in[9];
    float* out = (float*)d_out;

    convert_kernel<<<1280, 256>>>(x, Wq, Wk, Wv, Wo);

    dim3 qkvGrid(NTOK / 128, CCH / 128, 3);
    gemm_qkv_kernel<<<qkvGrid, 256>>>(bq, bk, bv);

    dim3 attnGrid(NTOK / TQ, NHEAD, 1);
    attn_mma_kernel<<<attnGrid, 256>>>();

    dim3 oGrid(NTOK / 128, CCH / 128, 1);
    gemm_o_kernel<<<oGrid, 256>>>(x, bo, gamma, out);
}

// round 5
// speedup vs baseline: 8.0501x; 1.3177x over previous
#include <cuda_runtime.h>
#include <cuda_bf16.h>
#include <cstdint>

// Problem constants: B=1, C=256, N=16*16*16=4096, heads=8, d=32
#define NTOK 4096
#define CCH  256
#define NHEAD 8
#define HDIM 32

// log2(e)/sqrt(32): folded into q so softmax uses ex2 directly
#define QSCALE 0.25503482617f

// ---------------- device scratch (no allocation allowed) ----------------
__device__ __align__(16) __nv_bfloat16 g_xb[CCH * NTOK];          // x bf16, [c][n]
__device__ __align__(16) __nv_bfloat16 g_Wb[4 * CCH * CCH];       // Wq|Wk|Wv|Wo bf16
__device__ __align__(16) __nv_bfloat16 g_qb[NHEAD * NTOK * HDIM]; // [h][n][d], pre-scaled
__device__ __align__(16) __nv_bfloat16 g_kb[NHEAD * NTOK * HDIM];
__device__ __align__(16) __nv_bfloat16 g_vb[NHEAD * NTOK * HDIM];
__device__ __align__(16) __nv_bfloat16 g_attnb[NTOK * CCH];       // [n][c]

// ---------------- helpers ----------------
__device__ __forceinline__ uint32_t sptr(const void* p) {
    return (uint32_t)__cvta_generic_to_shared(p);
}
__device__ __forceinline__ void ldm_x4(uint32_t& r0, uint32_t& r1, uint32_t& r2, uint32_t& r3, uint32_t addr) {
    asm volatile("ldmatrix.sync.aligned.m8n8.x4.shared.b16 {%0,%1,%2,%3}, [%4];"
                 : "=r"(r0), "=r"(r1), "=r"(r2), "=r"(r3) : "r"(addr));
}
__device__ __forceinline__ void ldm_x4t(uint32_t& r0, uint32_t& r1, uint32_t& r2, uint32_t& r3, uint32_t addr) {
    asm volatile("ldmatrix.sync.aligned.m8n8.x4.trans.shared.b16 {%0,%1,%2,%3}, [%4];"
                 : "=r"(r0), "=r"(r1), "=r"(r2), "=r"(r3) : "r"(addr));
}
__device__ __forceinline__ void mma_bf16(float* c, uint32_t a0, uint32_t a1, uint32_t a2, uint32_t a3,
                                         uint32_t b0, uint32_t b1) {
    asm volatile("mma.sync.aligned.m16n8k16.row.col.f32.bf16.bf16.f32 "
                 "{%0,%1,%2,%3}, {%4,%5,%6,%7}, {%8,%9}, {%0,%1,%2,%3};"
                 : "+f"(c[0]), "+f"(c[1]), "+f"(c[2]), "+f"(c[3])
                 : "r"(a0), "r"(a1), "r"(a2), "r"(a3), "r"(b0), "r"(b1));
}
__device__ __forceinline__ uint32_t pack_bf16x2(float hi, float lo) {
    uint32_t d;
    asm volatile("cvt.rn.bf16x2.f32 %0, %1, %2;" : "=r"(d) : "f"(hi), "f"(lo));
    return d;
}
__device__ __forceinline__ float ex2f(float x) {
    float y;
    asm volatile("ex2.approx.f32 %0, %1;" : "=f"(y) : "f"(x));
    return y;
}
__device__ __forceinline__ void cp16(uint32_t dst, const void* src) {
    asm volatile("cp.async.cg.shared.global [%0], [%1], 16;" :: "r"(dst), "l"(src));
}
__device__ __forceinline__ void cp_commit() {
    asm volatile("cp.async.commit_group;");
}
template <int N>
__device__ __forceinline__ void cp_wait() {
    asm volatile("cp.async.wait_group %0;" :: "n"(N));
}

// ---------------------------------------------------------------------------
// Convert x + 4 weight matrices fp32 -> bf16.
// total float4s: 262144 (x) + 4*16384 (W) = 327680 -> 1280 blocks x 256 thr
// ---------------------------------------------------------------------------
__global__ void __launch_bounds__(256) convert_kernel(
    const float* __restrict__ x,
    const float* __restrict__ Wq, const float* __restrict__ Wk,
    const float* __restrict__ Wv, const float* __restrict__ Wo)
{
    int i4 = blockIdx.x * 256 + threadIdx.x;
    const float* src;
    __nv_bfloat16* dst;
    int off4;
    if (i4 < 262144) { src = x; dst = g_xb; off4 = i4; }
    else {
        int j = i4 - 262144;
        int r = j >> 14;
        off4 = j & 16383;
        src = (r == 0) ? Wq : (r == 1) ? Wk : (r == 2) ? Wv : Wo;
        dst = g_Wb + r * (CCH * CCH);
    }
    float4 v = ((const float4*)src)[off4];
    __nv_bfloat162 lo = __floats2bfloat162_rn(v.x, v.y);
    __nv_bfloat162 hi = __floats2bfloat162_rn(v.z, v.w);
    uint2 pk;
    pk.x = *(uint32_t*)&lo;
    pk.y = *(uint32_t*)&hi;
    *(uint2*)&dst[off4 * 4] = pk;
}

// ---------------------------------------------------------------------------
// QKV projection with bf16 mma: out[o][n] = sum_c W[o][c] * x[c][n] + b[o]
// CTA tile 128(m) x 128(n), K in 32-chunks, cp.async double-buffered.
// 8 warps as 4(m) x 2(n), warp tile 32x64. Output bf16 [h][n][d]; q scaled.
// ---------------------------------------------------------------------------
__global__ void __launch_bounds__(256, 2) gemm_qkv_kernel(
    const float* __restrict__ bq, const float* __restrict__ bk, const float* __restrict__ bv)
{
    const __nv_bfloat16* W; const float* bias; __nv_bfloat16* outp; float sc;
    if (blockIdx.z == 0)      { W = g_Wb;                 bias = bq; outp = g_qb; sc = QSCALE; }
    else if (blockIdx.z == 1) { W = g_Wb + CCH * CCH;     bias = bk; outp = g_kb; sc = 1.0f; }
    else                      { W = g_Wb + 2 * CCH * CCH; bias = bv; outp = g_vb; sc = 1.0f; }

    __shared__ __nv_bfloat16 As[2][128 * 40];   // [m][k], pad->40
    __shared__ __nv_bfloat16 Bs[2][32 * 136];   // [k][n], pad->136

    const int tid  = threadIdx.x;
    const int lane = tid & 31;
    const int wid  = tid >> 5;
    const int wm   = wid & 3;
    const int wn   = wid >> 2;
    const int o0   = blockIdx.y * 128;
    const int n0   = blockIdx.x * 128;

    const int arow = tid >> 2, ac4 = tid & 3;    // A: rows arow, arow+64; 16B chunk ac4
    const int brow = tid >> 4, bc4 = tid & 15;   // B: rows brow, brow+16

    auto issue = [&](int s, int b) {
        const char* wsrc = (const char*)W + (size_t)(o0 + arow) * CCH * 2 + s * 64 + ac4 * 16;
        cp16(sptr(&As[b][arow * 40]) + ac4 * 16, wsrc);
        cp16(sptr(&As[b][(arow + 64) * 40]) + ac4 * 16, wsrc + (size_t)64 * CCH * 2);
        const char* xsrc = (const char*)g_xb + (size_t)(s * 32 + brow) * NTOK * 2 + (size_t)n0 * 2 + bc4 * 16;
        cp16(sptr(&Bs[b][brow * 136]) + bc4 * 16, xsrc);
        cp16(sptr(&Bs[b][(brow + 16) * 136]) + bc4 * 16, xsrc + (size_t)16 * NTOK * 2);
        cp_commit();
    };
    issue(0, 0);
    issue(1, 1);

    float acc[2][8][4];
    #pragma unroll
    for (int i = 0; i < 2; i++)
        #pragma unroll
        for (int j = 0; j < 8; j++)
            #pragma unroll
            for (int r = 0; r < 4; r++) acc[i][j][r] = 0.0f;

    for (int s = 0; s < 8; s++) {
        if (s == 7) cp_wait<0>(); else cp_wait<1>();
        __syncthreads();
        const int cur = s & 1;
        const uint32_t asb = sptr(As[cur]);
        const uint32_t bsb = sptr(Bs[cur]);

        #pragma unroll
        for (int ks = 0; ks < 2; ks++) {
            uint32_t a[2][4];
            #pragma unroll
            for (int mi = 0; mi < 2; mi++) {
                int row = wm * 32 + mi * 16 + (lane & 15);
                int col = (lane >> 4) * 8 + ks * 16;
                ldm_x4(a[mi][0], a[mi][1], a[mi][2], a[mi][3], asb + (uint32_t)(row * 40 + col) * 2);
            }
            uint32_t b[4][4];
            #pragma unroll
            for (int nq = 0; nq < 4; nq++) {
                int krow = ks * 16 + (lane & 7) + ((lane & 8) ? 8 : 0);
                int ncol = wn * 64 + nq * 16 + ((lane & 16) ? 8 : 0);
                ldm_x4t(b[nq][0], b[nq][1], b[nq][2], b[nq][3], bsb + (uint32_t)(krow * 136 + ncol) * 2);
            }
            #pragma unroll
            for (int mi = 0; mi < 2; mi++)
                #pragma unroll
                for (int nj = 0; nj < 8; nj++) {
                    int nq = nj >> 1, sel = nj & 1;
                    mma_bf16(acc[mi][nj], a[mi][0], a[mi][1], a[mi][2], a[mi][3],
                             b[nq][2 * sel], b[nq][2 * sel + 1]);
                }
        }
        __syncthreads();
        if (s + 2 < 8) issue(s + 2, cur);
    }

    // epilogue: bias + scale, write bf16 [h][n][d]
    float bz[2][2];
    #pragma unroll
    for (int mi = 0; mi < 2; mi++)
        #pragma unroll
        for (int hh = 0; hh < 2; hh++)
            bz[mi][hh] = bias[o0 + wm * 32 + mi * 16 + (lane >> 2) + 8 * hh];

    #pragma unroll
    for (int mi = 0; mi < 2; mi++)
        #pragma unroll
        for (int nj = 0; nj < 8; nj++)
            #pragma unroll
            for (int r = 0; r < 4; r++) {
                int m = o0 + wm * 32 + mi * 16 + (lane >> 2) + (r >> 1) * 8;
                int n = n0 + wn * 64 + nj * 8 + 2 * (lane & 3) + (r & 1);
                float v = (acc[mi][nj][r] + bz[mi][r >> 1]) * sc;
                outp[((m >> 5) << 17) + n * HDIM + (m & 31)] = __float2bfloat16(v);
            }
}

// ---------------------------------------------------------------------------
// Flash attention, bf16 mma, ex2 softmax (no max subtraction; scores bounded).
// cp.async 3-stage pipeline, ONE __syncthreads per 64-key tile.
// CTA: 128 queries x one head, 8 warps x 16 rows. Output bf16 [n][c].
// ---------------------------------------------------------------------------
#define TQ 128
#define TK 64
#define PADS 40

__global__ void __launch_bounds__(256, 2) attn_mma_kernel()
{
    const int h    = blockIdx.y;
    const int q0   = blockIdx.x * TQ;
    const int tid  = threadIdx.x;
    const int wid  = tid >> 5;
    const int lane = tid & 31;

    const __nv_bfloat16* __restrict__ qh = g_qb + (h << 17);
    const __nv_bfloat16* __restrict__ kh = g_kb + (h << 17);
    const __nv_bfloat16* __restrict__ vh = g_vb + (h << 17);

    __shared__ __nv_bfloat16 Qs[TQ * PADS];
    __shared__ __nv_bfloat16 Ks[3][TK * PADS];
    __shared__ __nv_bfloat16 Vs[3][TK * PADS];

    const int prow = tid >> 2, pch = tid & 3;   // 64 rows x 4 chunks of 16B

    auto issue = [&](int kt, int b) {
        const char* ksrc = (const char*)kh + (size_t)kt * TK * HDIM * 2 + prow * 64 + pch * 16;
        const char* vsrc = (const char*)vh + (size_t)kt * TK * HDIM * 2 + prow * 64 + pch * 16;
        cp16(sptr(&Ks[b][prow * PADS]) + pch * 16, ksrc);
        cp16(sptr(&Vs[b][prow * PADS]) + pch * 16, vsrc);
        cp_commit();
    };
    issue(0, 0);
    issue(1, 1);

    // load Q tile (128 x 32 bf16) with plain loads (overlaps with cp.async)
    {
        const uint4* qsrc = (const uint4*)(qh + q0 * HDIM);
        #pragma unroll
        for (int t = 0; t < 2; t++) {
            int idx = tid + t * 256;
            int row = idx >> 2, ch = idx & 3;
            *(uint4*)((char*)Qs + row * (PADS * 2) + ch * 16) = qsrc[idx];
        }
    }
    __syncthreads();

    uint32_t qa[2][4];
    {
        const uint32_t qbase = sptr(Qs);
        #pragma unroll
        for (int ks = 0; ks < 2; ks++) {
            int row = wid * 16 + (lane & 15);
            int col = (lane >> 4) * 8 + ks * 16;
            ldm_x4(qa[ks][0], qa[ks][1], qa[ks][2], qa[ks][3],
                   qbase + (uint32_t)(row * PADS + col) * 2);
        }
    }

    float o_[4][4];
    #pragma unroll
    for (int i = 0; i < 4; i++)
        #pragma unroll
        for (int j = 0; j < 4; j++) o_[i][j] = 0.0f;
    float l0 = 0.0f, l1 = 0.0f;

    int cur = 0;
    for (int kt = 0; kt < NTOK / TK; kt++) {
        if (kt == NTOK / TK - 1) cp_wait<0>(); else cp_wait<1>();
        __syncthreads();
        // overwrite of buf (kt+2)%3 is safe: its last readers (tile kt-1)
        // all passed the barrier above.
        if (kt + 2 < NTOK / TK) {
            int nb = cur + 2; if (nb >= 3) nb -= 3;
            issue(kt + 2, nb);
        }
        const uint32_t ksb = sptr(Ks[cur]);
        const uint32_t vsb = sptr(Vs[cur]);
        cur++; if (cur == 3) cur = 0;

        // S = Q K^T  (q pre-scaled by log2e/sqrt(d))
        float s[8][4];
        #pragma unroll
        for (int j = 0; j < 8; j++) {
            s[j][0] = s[j][1] = s[j][2] = s[j][3] = 0.0f;
            uint32_t k0, k1, k2, k3;
            uint32_t addr = ksb + (uint32_t)((8 * j + (lane & 7)) * PADS + (lane >> 3) * 8) * 2;
            ldm_x4(k0, k1, k2, k3, addr);
            mma_bf16(s[j], qa[0][0], qa[0][1], qa[0][2], qa[0][3], k0, k1);
            mma_bf16(s[j], qa[1][0], qa[1][1], qa[1][2], qa[1][3], k2, k3);
        }

        // p = 2^s, accumulate row sums, pack bf16
        uint32_t pa[8][2];
        #pragma unroll
        for (int j = 0; j < 8; j++) {
            float p0 = ex2f(s[j][0]);
            float p1 = ex2f(s[j][1]);
            float p2 = ex2f(s[j][2]);
            float p3 = ex2f(s[j][3]);
            l0 += p0 + p1;
            l1 += p2 + p3;
            pa[j][0] = pack_bf16x2(p1, p0);
            pa[j][1] = pack_bf16x2(p3, p2);
        }

        // O += P V
        #pragma unroll
        for (int c = 0; c < 4; c++) {
            uint32_t vb[8];
            uint32_t keyrow = 16 * c + (lane & 7) + ((lane & 8) ? 8 : 0);
            uint32_t dofs   = (lane & 16) ? 8 : 0;
            uint32_t addrA  = vsb + (uint32_t)(keyrow * PADS + dofs) * 2;
            ldm_x4t(vb[0], vb[1], vb[2], vb[3], addrA);
            ldm_x4t(vb[4], vb[5], vb[6], vb[7], addrA + 32);
            #pragma unroll
            for (int dt = 0; dt < 4; dt++) {
                mma_bf16(o_[dt], pa[2 * c][0], pa[2 * c][1], pa[2 * c + 1][0], pa[2 * c + 1][1],
                         vb[2 * dt], vb[2 * dt + 1]);
            }
        }
    }

    // finalize
    l0 += __shfl_xor_sync(0xffffffffu, l0, 1);
    l0 += __shfl_xor_sync(0xffffffffu, l0, 2);
    l1 += __shfl_xor_sync(0xffffffffu, l1, 1);
    l1 += __shfl_xor_sync(0xffffffffu, l1, 2);
    const float inv0 = 1.0f / l0;
    const float inv1 = 1.0f / l1;

    const int r0 = q0 + wid * 16 + (lane >> 2);
    const int r1 = r0 + 8;
    const int cbase = h * 32 + 2 * (lane & 3);
    #pragma unroll
    for (int dt = 0; dt < 4; dt++) {
        int c = cbase + dt * 8;
        __nv_bfloat162 v0 = __floats2bfloat162_rn(o_[dt][0] * inv0, o_[dt][1] * inv0);
        __nv_bfloat162 v1 = __floats2bfloat162_rn(o_[dt][2] * inv1, o_[dt][3] * inv1);
        *(uint32_t*)&g_attnb[r0 * CCH + c] = *(uint32_t*)&v0;
        *(uint32_t*)&g_attnb[r1 * CCH + c] = *(uint32_t*)&v1;
    }
}

// ---------------------------------------------------------------------------
// O projection + residual, bf16 mma, 64(m) x 128(n) tiles -> 128 CTAs:
// out[o][n] = x[o][n] + gamma * (sum_c Wo[o][c]*attn[c][n] + bo[o])
// B = g_attnb [n][c] (k-contig rows -> plain ldmatrix). cp.async 3-stage.
// ---------------------------------------------------------------------------
__global__ void __launch_bounds__(256, 2) gemm_o_kernel(
    const float* __restrict__ x,
    const float* __restrict__ bo, const float* __restrict__ gamma,
    float* __restrict__ out)
{
    const __nv_bfloat16* W = g_Wb + 3 * CCH * CCH;

    __shared__ __nv_bfloat16 As[3][64 * 40];    // [m][k]
    __shared__ __nv_bfloat16 Bs[3][128 * 40];   // [n][k]

    const int tid  = threadIdx.x;
    const int lane = tid & 31;
    const int wid  = tid >> 5;
    const int wm   = wid & 1;     // 2 m-groups of 32 rows
    const int wn   = wid >> 1;    // 4 n-groups of 32 cols
    const int o0   = blockIdx.y * 64;
    const int n0   = blockIdx.x * 128;

    const int arow = tid >> 2, ac4 = tid & 3;

    auto issue = [&](int s, int b) {
        const char* wsrc = (const char*)W + (size_t)(o0 + arow) * CCH * 2 + s * 64 + ac4 * 16;
        if (arow < 64) { /* all arow in 0..63 */ }
        cp16(sptr(&As[b][arow * 40]) + ac4 * 16, wsrc);
        const char* bsrc = (const char*)g_attnb + (size_t)(n0 + arow) * CCH * 2 + s * 64 + ac4 * 16;
        cp16(sptr(&Bs[b][arow * 40]) + ac4 * 16, bsrc);
        cp16(sptr(&Bs[b][(arow + 64) * 40]) + ac4 * 16, bsrc + (size_t)64 * CCH * 2);
        cp_commit();
    };
    issue(0, 0);
    issue(1, 1);

    float acc[2][4][4];
    #pragma unroll
    for (int i = 0; i < 2; i++)
        #pragma unroll
        for (int j = 0; j < 4; j++)
            #pragma unroll
            for (int r = 0; r < 4; r++) acc[i][j][r] = 0.0f;

    int cur = 0;
    for (int s = 0; s < 8; s++) {
        if (s == 7) cp_wait<0>(); else cp_wait<1>();
        __syncthreads();
        if (s + 2 < 8) {
            int nb = cur + 2; if (nb >= 3) nb -= 3;
            issue(s + 2, nb);
        }
        const uint32_t asb = sptr(As[cur]);
        const uint32_t bsb = sptr(Bs[cur]);
        cur++; if (cur == 3) cur = 0;

        uint32_t b[4][4];
        #pragma unroll
        for (int nt = 0; nt < 4; nt++) {
            uint32_t addr = bsb + (uint32_t)((wn * 32 + nt * 8 + (lane & 7)) * 40 + (lane >> 3) * 8) * 2;
            ldm_x4(b[nt][0], b[nt][1], b[nt][2], b[nt][3], addr);
        }
        #pragma unroll
        for (int ks = 0; ks < 2; ks++) {
            uint32_t a[2][4];
            #pragma unroll
            for (int mi = 0; mi < 2; mi++) {
                int row = wm * 32 + mi * 16 + (lane & 15);
                int col = (lane >> 4) * 8 + ks * 16;
                ldm_x4(a[mi][0], a[mi][1], a[mi][2], a[mi][3], asb + (uint32_t)(row * 40 + col) * 2);
            }
            #pragma unroll
            for (int mi = 0; mi < 2; mi++)
                #pragma unroll
                for (int nt = 0; nt < 4; nt++)
                    mma_bf16(acc[mi][nt], a[mi][0], a[mi][1], a[mi][2], a[mi][3],
                             b[nt][2 * ks], b[nt][2 * ks + 1]);
        }
    }

    const float g = gamma[0];
    float bz[2][2];
    #pragma unroll
    for (int mi = 0; mi < 2; mi++)
        #pragma unroll
        for (int hh = 0; hh < 2; hh++)
            bz[mi][hh] = bo[o0 + wm * 32 + mi * 16 + (lane >> 2) + 8 * hh];

    #pragma unroll
    for (int mi = 0; mi < 2; mi++)
        #pragma unroll
        for (int nt = 0; nt < 4; nt++) {
            int m = o0 + wm * 32 + mi * 16 + (lane >> 2);
            int n = n0 + wn * 32 + nt * 8 + 2 * (lane & 3);
            {
                float2 xv = *(const float2*)&x[m * NTOK + n];
                float2 ov;
                ov.x = xv.x + g * (acc[mi][nt][0] + bz[mi][0]);
                ov.y = xv.y + g * (acc[mi][nt][1] + bz[mi][0]);
                *(float2*)&out[m * NTOK + n] = ov;
            }
            {
                int m2 = m + 8;
                float2 xv = *(const float2*)&x[m2 * NTOK + n];
                float2 ov;
                ov.x = xv.x + g * (acc[mi][nt][2] + bz[mi][1]);
                ov.y = xv.y + g * (acc[mi][nt][3] + bz[mi][1]);
                *(float2*)&out[m2 * NTOK + n] = ov;
            }
        }
}

// ---------------------------------------------------------------------------
// Launch: inputs x, Wq, bq, Wk, bk, Wv, bv, Wo, bo, gamma
// ---------------------------------------------------------------------------
extern "C" void kernel_launch(void* const* d_in, const int* in_sizes, int n_in,
                              void* d_out, int out_size)
{
    const float* x     = (const float*)d_in[0];
    const float* Wq    = (const float*)d_in[1];
    const float* bq    = (const float*)d_in[2];
    const float* Wk    = (const float*)d_in[3];
    const float* bk    = (const float*)d_in[4];
    const float* Wv    = (const float*)d_in[5];
    const float* bv    = (const float*)d_in[6];
    const float* Wo    = (const float*)d_in[7];
    const float* bo    = (const float*)d_in[8];
    const float* gamma = (const float*)d_in[9];
    float* out = (float*)d_out;

    convert_kernel<<<1280, 256>>>(x, Wq, Wk, Wv, Wo);

    dim3 qkvGrid(NTOK / 128, CCH / 128, 3);
    gemm_qkv_kernel<<<qkvGrid, 256>>>(bq, bk, bv);

    dim3 attnGrid(NTOK / TQ, NHEAD, 1);
    attn_mma_kernel<<<attnGrid, 256>>>();

    dim3 oGrid(NTOK / 128, CCH / 64, 1);
    gemm_o_kernel<<<oGrid, 256>>>(x, bo, gamma, out);
}